// round 10
// baseline (speedup 1.0000x reference)
#include <cuda_runtime.h>

// Malvar-He-Cutler demosaic, GB300 (sm_103a). Round 10:
// R9 (no smem, direct aligned LDG.128, basis accumulation, streamed stores)
// with the accumulator set trimmed to exactly what the horizontal combos
// need: a[4] (cols 2-5), b[6] (cols 1-6), c[8] per output row -> 36 floats
// instead of 48. __launch_bounds__(256,4): 64-reg cap -> 4 CTAs/SM.

__device__ __forceinline__ float clip01(float v) {
    return fminf(fmaxf(v, 0.0f), 1.0f);
}
__device__ __forceinline__ int refl(int i, int n) {
    i = (i < 0) ? -i : i;
    return (i >= n) ? (2 * n - 2 - i) : i;
}

__global__ void __launch_bounds__(256, 4)
demosaic_kernel(const float* __restrict__ x, float* __restrict__ out,
                int H, int W)
{
    const int tx = threadIdx.x;                    // 0..31: col quad within block
    const int ty = threadIdx.y;                    // 0..7 : row pair within block
    const int base_c = (blockIdx.x * 32 + tx) * 4; // first output col (mult of 4)
    const int gr0    = (blockIdx.y * 8 + ty) * 2;  // first output row (even)
    if (base_c >= W || gr0 >= H) return;

    const bool fast = (gr0 >= 2) & (gr0 + 3 < H) & (base_c >= 4) & (base_c + 8 <= W);

    // Trimmed vertical bases over window cols [base_c-2, base_c+6):
    //  even row: a[k]=cols k+2 (v0+v4), b[k]=cols k+1 (v1+v3), c[k]=cols k (v2)
    //  odd  row: A[k]=cols k+2 (v1+v5), B[k]=cols k+1 (v2+v4), Cv[k]=cols k (v3)
    float a[4], b[6], c[8], A[4], B[6], Cv[8];

#define ACCUM(J)                                                              \
    {                                                                         \
        if (J == 0) { _Pragma("unroll") for (int i = 2; i < 6; ++i) a[i-2]  = r[i]; } \
        else if (J == 1) {                                                    \
            _Pragma("unroll") for (int i = 1; i < 7; ++i) b[i-1]  = r[i];     \
            _Pragma("unroll") for (int i = 2; i < 6; ++i) A[i-2]  = r[i];     \
        }                                                                     \
        else if (J == 2) {                                                    \
            _Pragma("unroll") for (int i = 0; i < 8; ++i) c[i]    = r[i];     \
            _Pragma("unroll") for (int i = 1; i < 7; ++i) B[i-1]  = r[i];     \
        }                                                                     \
        else if (J == 3) {                                                    \
            _Pragma("unroll") for (int i = 0; i < 8; ++i) Cv[i]   = r[i];     \
            _Pragma("unroll") for (int i = 1; i < 7; ++i) b[i-1] += r[i];     \
        }                                                                     \
        else if (J == 4) {                                                    \
            _Pragma("unroll") for (int i = 2; i < 6; ++i) a[i-2] += r[i];     \
            _Pragma("unroll") for (int i = 1; i < 7; ++i) B[i-1] += r[i];     \
        }                                                                     \
        else { _Pragma("unroll") for (int i = 2; i < 6; ++i) A[i-2] += r[i]; } \
    }

    if (fast) {
        const float* rp = x + (size_t)(gr0 - 2) * W + (base_c - 4);
        #pragma unroll
        for (int j = 0; j < 6; ++j) {
            const float4 u = *reinterpret_cast<const float4*>(rp);
            const float4 v = *reinterpret_cast<const float4*>(rp + 4);
            const float4 w = *reinterpret_cast<const float4*>(rp + 8);
            rp += W;
            // window col i (0..7) = loaded float index i+2
            const float r[8] = {u.z, u.w, v.x, v.y, v.z, v.w, w.x, w.y};
            ACCUM(j)
        }
    } else {
        #pragma unroll
        for (int j = 0; j < 6; ++j) {
            const float* rp = x + (size_t)refl(gr0 - 2 + j, H) * W;
            float r[8];
            #pragma unroll
            for (int i = 0; i < 8; ++i)
                r[i] = rp[refl(base_c - 2 + i, W)];
            ACCUM(j)
        }
    }
#undef ACCUM

    // ---- Row 0 (even global row): R Gr R Gr ----
    {
        float o[12];
        #pragma unroll
        for (int p = 0; p < 4; ++p) {
            const int q = p + 2;
            const float cc = c[q], bb = b[q-1], aa = a[q-2];
            const float s1 = c[q-1] + c[q+1];
            const float s2 = c[q-2] + c[q+2];
            const float s3 = b[q-2] + b[q];
            const float gi  = 0.125f * (4.0f*cc + 2.0f*(bb + s1) - (aa + s2));
            const float rgr = 0.125f * (5.0f*cc + 4.0f*s1 - s2 + 0.5f*aa - s3);
            const float rgv = 0.125f * (5.0f*cc + 4.0f*bb - aa + 0.5f*s2 - s3);
            const float rb  = 0.125f * (6.0f*cc + 2.0f*s3 - 1.5f*(aa + s2));
            if ((p & 1) == 0) { o[3*p]=clip01(cc);  o[3*p+1]=clip01(gi); o[3*p+2]=clip01(rb);  }
            else              { o[3*p]=clip01(rgr); o[3*p+1]=clip01(cc); o[3*p+2]=clip01(rgv); }
        }
        if (base_c + 4 <= W) {
            float4* d4 = reinterpret_cast<float4*>(out + ((size_t)gr0 * W + base_c) * 3);
            __stcs(d4 + 0, make_float4(o[0], o[1], o[2],  o[3]));
            __stcs(d4 + 1, make_float4(o[4], o[5], o[6],  o[7]));
            __stcs(d4 + 2, make_float4(o[8], o[9], o[10], o[11]));
        } else {
            #pragma unroll
            for (int p = 0; p < 4; ++p)
                if (base_c + p < W) {
                    float* q2 = out + ((size_t)gr0 * W + base_c + p) * 3;
                    q2[0] = o[3*p]; q2[1] = o[3*p+1]; q2[2] = o[3*p+2];
                }
        }
    }

    // ---- Row 1 (odd global row): Gb B Gb B ----
    {
        float o[12];
        #pragma unroll
        for (int p = 0; p < 4; ++p) {
            const int q = p + 2;
            const float cc = Cv[q], bb = B[q-1], aa = A[q-2];
            const float s1 = Cv[q-1] + Cv[q+1];
            const float s2 = Cv[q-2] + Cv[q+2];
            const float s3 = B[q-2] + B[q];
            const float gi  = 0.125f * (4.0f*cc + 2.0f*(bb + s1) - (aa + s2));
            const float rgr = 0.125f * (5.0f*cc + 4.0f*s1 - s2 + 0.5f*aa - s3);
            const float rgv = 0.125f * (5.0f*cc + 4.0f*bb - aa + 0.5f*s2 - s3);
            const float rb  = 0.125f * (6.0f*cc + 2.0f*s3 - 1.5f*(aa + s2));
            if ((p & 1) == 0) { o[3*p]=clip01(rgv); o[3*p+1]=clip01(cc); o[3*p+2]=clip01(rgr); }
            else              { o[3*p]=clip01(rb);  o[3*p+1]=clip01(gi); o[3*p+2]=clip01(cc);  }
        }
        const int gr1 = gr0 + 1;
        if (gr1 < H) {
            if (base_c + 4 <= W) {
                float4* d4 = reinterpret_cast<float4*>(out + ((size_t)gr1 * W + base_c) * 3);
                __stcs(d4 + 0, make_float4(o[0], o[1], o[2],  o[3]));
                __stcs(d4 + 1, make_float4(o[4], o[5], o[6],  o[7]));
                __stcs(d4 + 2, make_float4(o[8], o[9], o[10], o[11]));
            } else {
                #pragma unroll
                for (int p = 0; p < 4; ++p)
                    if (base_c + p < W) {
                        float* q2 = out + ((size_t)gr1 * W + base_c + p) * 3;
                        q2[0] = o[3*p]; q2[1] = o[3*p+1]; q2[2] = o[3*p+2];
                    }
            }
        }
    }
}

extern "C" void kernel_launch(void* const* d_in, const int* in_sizes, int n_in,
                              void* d_out, int out_size)
{
    const float* x = (const float*)d_in[0];
    long nx = in_sizes[0];
    if (n_in > 1 && in_sizes[1] > in_sizes[0]) {  // defensive: pick the big tensor as x
        x = (const float*)d_in[1];
        nx = in_sizes[1];
    }

    const int W = 6144;
    const int H = (int)(nx / W);

    dim3 block(32, 8);                         // 128 cols x 16 rows per block
    dim3 grid((unsigned)((W + 127) / 128),
              (unsigned)((H + 15) / 16));

    demosaic_kernel<<<grid, block>>>(x, (float*)d_out, H, W);
}

// round 11
// speedup vs baseline: 1.7100x; 1.7100x over previous
#include <cuda_runtime.h>

// Malvar-He-Cutler demosaic, GB300 (sm_103a). Round 11:
// R9 structure, but the 8-col window is built from: own 4 cols (6 aligned
// LDG.128, zero over-fetch) + halo bases from neighbor lanes via 12 shfl
// (shfl pipe, not L1). Lanes 0/31 load the block-edge halo themselves.
// Load wavefronts per warp: 72 -> ~36. Rows use unconditional reflect
// indices (own-col loads are never OOB), so no fast/slow divergence.

__device__ __forceinline__ float clip01(float v) {
    return fminf(fmaxf(v, 0.0f), 1.0f);
}
__device__ __forceinline__ int refl(int i, int n) {
    i = (i < 0) ? -i : i;
    return (i >= n) ? (2 * n - 2 - i) : i;
}

__global__ void __launch_bounds__(256, 3)
demosaic_kernel(const float* __restrict__ x, float* __restrict__ out,
                int H, int W)
{
    const unsigned FM = 0xffffffffu;
    const int tx = threadIdx.x;                    // lane 0..31
    const int ty = threadIdx.y;                    // 0..7
    const int base_c = (blockIdx.x * 32 + tx) * 4; // own cols base_c..base_c+3
    const int gr0    = (blockIdx.y * 8 + ty) * 2;  // output rows gr0, gr0+1

    // Reflected row indices for the 6-row window (always valid).
    int rows[6];
    #pragma unroll
    for (int j = 0; j < 6; ++j) rows[j] = refl(gr0 - 2 + j, H);

    // Defensive col clamp for own loads (no-op for W % 128 == 0).
    const int bc_ld = (base_c + 4 <= W) ? base_c : (W - 4);

    // ---- own 4-col loads: 6 aligned LDG.128 ----
    float4 rv[6];
    #pragma unroll
    for (int j = 0; j < 6; ++j)
        rv[j] = *reinterpret_cast<const float4*>(x + (size_t)rows[j] * W + bc_ld);

    // ---- edge-lane halo loads (2 cols x 6 rows) ----
    const bool is_l = (tx == 0), is_r = (tx == 31);
    float2 hv[6];
    if (is_l | is_r) {
        const int hcol = is_l ? (base_c - 2) : (base_c + 4);
        if (hcol >= 0 && hcol + 2 <= W) {
            #pragma unroll
            for (int j = 0; j < 6; ++j)
                hv[j] = *reinterpret_cast<const float2*>(x + (size_t)rows[j] * W + hcol);
        } else {
            const int h0 = refl(hcol, W), h1 = refl(hcol + 1, W);
            #pragma unroll
            for (int j = 0; j < 6; ++j) {
                hv[j].x = x[(size_t)rows[j] * W + h0];
                hv[j].y = x[(size_t)rows[j] * W + h1];
            }
        }
    }

    // ---- vertical bases over own 4 cols ----
    // even out row (gr0):  ae=v0+v4, be=v1+v3, ce=v2
    // odd  out row (gr0+1): ao=v1+v5, bo=v2+v4, co=v3
    float ae[4], be[4], ce[4], ao[4], bo[4], co[4];
    {
        float r[6][4];
        #pragma unroll
        for (int j = 0; j < 6; ++j) {
            r[j][0] = rv[j].x; r[j][1] = rv[j].y; r[j][2] = rv[j].z; r[j][3] = rv[j].w;
        }
        #pragma unroll
        for (int i = 0; i < 4; ++i) {
            ae[i] = r[0][i] + r[4][i];
            be[i] = r[1][i] + r[3][i];
            ce[i] = r[2][i];
            ao[i] = r[1][i] + r[5][i];
            bo[i] = r[2][i] + r[4][i];
            co[i] = r[3][i];
        }
    }

    // ---- edge-lane halo bases (cols hcol, hcol+1) ----
    float hce0 = 0, hce1 = 0, hbe0 = 0, hbe1 = 0, hco0 = 0, hco1 = 0, hbo0 = 0, hbo1 = 0;
    if (is_l | is_r) {
        hce0 = hv[2].x;            hce1 = hv[2].y;
        hbe0 = hv[1].x + hv[3].x;  hbe1 = hv[1].y + hv[3].y;
        hco0 = hv[3].x;            hco1 = hv[3].y;
        hbo0 = hv[2].x + hv[4].x;  hbo1 = hv[2].y + hv[4].y;
    }

    // ---- halo bases via shuffle ----
    // left (cols base_c-2, base_c-1) from lane tx-1; right (cols +4, +5) from tx+1.
    float le_c0 = __shfl_up_sync(FM, ce[2], 1);    // c[-2]
    float le_c1 = __shfl_up_sync(FM, ce[3], 1);    // c[-1]
    float le_b  = __shfl_up_sync(FM, be[3], 1);    // b[-1]
    float lo_c0 = __shfl_up_sync(FM, co[2], 1);
    float lo_c1 = __shfl_up_sync(FM, co[3], 1);
    float lo_b  = __shfl_up_sync(FM, bo[3], 1);
    float re_c0 = __shfl_down_sync(FM, ce[0], 1);  // c[4]
    float re_c1 = __shfl_down_sync(FM, ce[1], 1);  // c[5]
    float re_b  = __shfl_down_sync(FM, be[0], 1);  // b[4]
    float ro_c0 = __shfl_down_sync(FM, co[0], 1);
    float ro_c1 = __shfl_down_sync(FM, co[1], 1);
    float ro_b  = __shfl_down_sync(FM, bo[0], 1);
    if (is_l) { le_c0 = hce0; le_c1 = hce1; le_b = hbe1;
                lo_c0 = hco0; lo_c1 = hco1; lo_b = hbo1; }
    if (is_r) { re_c0 = hce0; re_c1 = hce1; re_b = hbe0;
                ro_c0 = hco0; ro_c1 = hco1; ro_b = hbo0; }

    // ---- Row 0 (even global row): R Gr R Gr ----
    {
        // extended arrays: cx[i] = c at col i-2; bx[i] = b at col i-1
        const float cx[8] = {le_c0, le_c1, ce[0], ce[1], ce[2], ce[3], re_c0, re_c1};
        const float bx[6] = {le_b,  be[0], be[1], be[2], be[3], re_b};
        float o[12];
        #pragma unroll
        for (int p = 0; p < 4; ++p) {
            const float cc = cx[p+2], bb = bx[p+1], aa = ae[p];
            const float s1 = cx[p+1] + cx[p+3];
            const float s2 = cx[p]   + cx[p+4];
            const float s3 = bx[p]   + bx[p+2];
            const float gi  = 0.125f * (4.0f*cc + 2.0f*(bb + s1) - (aa + s2));
            const float rgr = 0.125f * (5.0f*cc + 4.0f*s1 - s2 + 0.5f*aa - s3);
            const float rgv = 0.125f * (5.0f*cc + 4.0f*bb - aa + 0.5f*s2 - s3);
            const float rb  = 0.125f * (6.0f*cc + 2.0f*s3 - 1.5f*(aa + s2));
            if ((p & 1) == 0) { o[3*p]=clip01(cc);  o[3*p+1]=clip01(gi); o[3*p+2]=clip01(rb);  }
            else              { o[3*p]=clip01(rgr); o[3*p+1]=clip01(cc); o[3*p+2]=clip01(rgv); }
        }
        if (gr0 < H && base_c + 4 <= W) {
            float4* d4 = reinterpret_cast<float4*>(out + ((size_t)gr0 * W + base_c) * 3);
            __stcs(d4 + 0, make_float4(o[0], o[1], o[2],  o[3]));
            __stcs(d4 + 1, make_float4(o[4], o[5], o[6],  o[7]));
            __stcs(d4 + 2, make_float4(o[8], o[9], o[10], o[11]));
        } else if (gr0 < H) {
            #pragma unroll
            for (int p = 0; p < 4; ++p)
                if (base_c + p < W) {
                    float* q2 = out + ((size_t)gr0 * W + base_c + p) * 3;
                    q2[0] = o[3*p]; q2[1] = o[3*p+1]; q2[2] = o[3*p+2];
                }
        }
    }

    // ---- Row 1 (odd global row): Gb B Gb B ----
    {
        const float cx[8] = {lo_c0, lo_c1, co[0], co[1], co[2], co[3], ro_c0, ro_c1};
        const float bx[6] = {lo_b,  bo[0], bo[1], bo[2], bo[3], ro_b};
        float o[12];
        #pragma unroll
        for (int p = 0; p < 4; ++p) {
            const float cc = cx[p+2], bb = bx[p+1], aa = ao[p];
            const float s1 = cx[p+1] + cx[p+3];
            const float s2 = cx[p]   + cx[p+4];
            const float s3 = bx[p]   + bx[p+2];
            const float gi  = 0.125f * (4.0f*cc + 2.0f*(bb + s1) - (aa + s2));
            const float rgr = 0.125f * (5.0f*cc + 4.0f*s1 - s2 + 0.5f*aa - s3);
            const float rgv = 0.125f * (5.0f*cc + 4.0f*bb - aa + 0.5f*s2 - s3);
            const float rb  = 0.125f * (6.0f*cc + 2.0f*s3 - 1.5f*(aa + s2));
            if ((p & 1) == 0) { o[3*p]=clip01(rgv); o[3*p+1]=clip01(cc); o[3*p+2]=clip01(rgr); }
            else              { o[3*p]=clip01(rb);  o[3*p+1]=clip01(gi); o[3*p+2]=clip01(cc);  }
        }
        const int gr1 = gr0 + 1;
        if (gr1 < H && base_c + 4 <= W) {
            float4* d4 = reinterpret_cast<float4*>(out + ((size_t)gr1 * W + base_c) * 3);
            __stcs(d4 + 0, make_float4(o[0], o[1], o[2],  o[3]));
            __stcs(d4 + 1, make_float4(o[4], o[5], o[6],  o[7]));
            __stcs(d4 + 2, make_float4(o[8], o[9], o[10], o[11]));
        } else if (gr1 < H) {
            #pragma unroll
            for (int p = 0; p < 4; ++p)
                if (base_c + p < W) {
                    float* q2 = out + ((size_t)gr1 * W + base_c + p) * 3;
                    q2[0] = o[3*p]; q2[1] = o[3*p+1]; q2[2] = o[3*p+2];
                }
        }
    }
}

extern "C" void kernel_launch(void* const* d_in, const int* in_sizes, int n_in,
                              void* d_out, int out_size)
{
    const float* x = (const float*)d_in[0];
    long nx = in_sizes[0];
    if (n_in > 1 && in_sizes[1] > in_sizes[0]) {  // defensive: pick the big tensor as x
        x = (const float*)d_in[1];
        nx = in_sizes[1];
    }

    const int W = 6144;
    const int H = (int)(nx / W);

    dim3 block(32, 8);                         // 128 cols x 16 rows per block
    dim3 grid((unsigned)((W + 127) / 128),
              (unsigned)((H + 15) / 16));

    demosaic_kernel<<<grid, block>>>(x, (float*)d_out, H, W);
}